// round 3
// baseline (speedup 1.0000x reference)
#include <cuda_runtime.h>
#include <stdint.h>

// Problem: NSF sine-source generator.
// Inputs: f0 [32,800] f32, W [9,1] f32, b [1] f32, upp=240 (int)
// Output: concat( har [32*192000], noise [32*192000], uv [32*192000] ) f32

#define SR_F 24000.0f
#define TWO_PI_F 6.2831853071795864769f

__device__ double g_prefix[32 * 800]; // exclusive frame prefix * upp (double)

// ---------------------------------------------------------------------------
// Kernel A: one block per batch row; thread 0 serially accumulates 800 frames.
// ---------------------------------------------------------------------------
__global__ void frame_prefix_kernel(const float* __restrict__ f0, int F, int upp) {
    const int b = blockIdx.x;
    if (threadIdx.x != 0) return;
    const float* row = f0 + b * F;
    double acc = 0.0;
    for (int j = 0; j < F; j++) {
        g_prefix[b * F + j] = acc * (double)upp;      // exclusive prefix
        acc += (double)(row[j] / SR_F);               // f32 division rounding
    }
}

// ---------------------------------------------------------------------------
// Kernel B: harmonic source + uv. Grid (F, B), blockDim = upp (=240).
// out index = (b*F + f)*upp + i -> fully coalesced, no integer divides.
// sin(h*theta) h=1..9 via Chebyshev recurrence from one sincosf.
// (Validated: rel_err 5.3e-6 in round 2.)
// ---------------------------------------------------------------------------
__global__ void har_uv_kernel(const float* __restrict__ f0,
                              const float* __restrict__ W,
                              const float* __restrict__ bias,
                              float* __restrict__ out,
                              int F, int upp, int N) {
    const int f = blockIdx.x;
    const int b = blockIdx.y;
    const int i = threadIdx.x;           // 0..upp-1
    const int fr = b * F + f;

    const float f0v = __ldg(&f0[fr]);
    const float uv = (f0v > 0.0f) ? 1.0f : 0.0f;
    const float c  = f0v / SR_F;

    const double base = g_prefix[fr] + (double)c * (double)(i + 1);
    const float basef = (float)base;                 // reference holds f32 base_phase
    const float theta = basef * TWO_PI_F;

    float s1, c1;
    sincosf(theta, &s1, &c1);
    const float c2 = 2.0f * c1;

    float sprev = 0.0f, scur = s1;
    float acc = 0.0f;
    #pragma unroll
    for (int h = 0; h < 9; h++) {
        acc = fmaf(0.1f * scur, __ldg(&W[h]), acc);  // SINE_AMP*sin(h*th)*W_h
        float snext = fmaf(c2, scur, -sprev);        // sin((h+1)*th)
        sprev = scur; scur = snext;
    }

    const float har = tanhf(fmaf(uv, acc, __ldg(bias)));  // uv in {0,1}
    const int idx = fr * upp + i;
    out[idx]         = har;   // har_source
    out[2 * N + idx] = uv;    // uv
}

// ---------------------------------------------------------------------------
// Kernel C: noise = jax.random.normal(key(1234)) * (0.1/3)
// PARTITIONABLE threefry (modern jax default): element i uses counter
// (hi,lo) = (0, i); 32-bit output = out_lane0 ^ out_lane1.
// ---------------------------------------------------------------------------
__device__ __forceinline__ uint32_t threefry_xor(uint32_t p0, uint32_t p1) {
    const uint32_t k0 = 0u, k1 = 1234u;
    const uint32_t k2 = k0 ^ k1 ^ 0x1BD11BDAu;
    uint32_t x0 = p0 + k0, x1 = p1 + k1;
#define TF_MIX(r) { x0 += x1; x1 = (x1 << (r)) | (x1 >> (32 - (r))); x1 ^= x0; }
    TF_MIX(13) TF_MIX(15) TF_MIX(26) TF_MIX(6)   x0 += k1; x1 += k2 + 1u;
    TF_MIX(17) TF_MIX(29) TF_MIX(16) TF_MIX(24)  x0 += k2; x1 += k0 + 2u;
    TF_MIX(13) TF_MIX(15) TF_MIX(26) TF_MIX(6)   x0 += k0; x1 += k1 + 3u;
    TF_MIX(17) TF_MIX(29) TF_MIX(16) TF_MIX(24)  x0 += k1; x1 += k2 + 4u;
    TF_MIX(13) TF_MIX(15) TF_MIX(26) TF_MIX(6)   x0 += k2; x1 += k0 + 5u;
#undef TF_MIX
    return x0 ^ x1;
}

__device__ __forceinline__ float bits_to_noise(uint32_t bits) {
    float u01 = __uint_as_float((bits >> 9) | 0x3f800000u) - 1.0f; // [0,1)
    const float lo = -0.99999994f;             // nextafterf(-1,0)
    float u = u01 * 2.0f + lo;                 // (hi-lo) rounds to 2.0f
    u = fmaxf(lo, u);
    float n = 1.4142135623730951f * erfinvf(u);
    return n * (float)(0.1 / 3.0);
}

__global__ void noise_kernel(float* __restrict__ out, int N) {
    const int i = (blockIdx.x * blockDim.x + threadIdx.x) * 4;
    if (i >= N) return;
    float4 v;
    v.x = bits_to_noise(threefry_xor(0u, (uint32_t)(i + 0)));
    v.y = bits_to_noise(threefry_xor(0u, (uint32_t)(i + 1)));
    v.z = bits_to_noise(threefry_xor(0u, (uint32_t)(i + 2)));
    v.w = bits_to_noise(threefry_xor(0u, (uint32_t)(i + 3)));
    *(float4*)(out + N + i) = v;
}

// ---------------------------------------------------------------------------
extern "C" void kernel_launch(void* const* d_in, const int* in_sizes, int n_in,
                              void* d_out, int out_size) {
    const float* f0   = (const float*)d_in[0];
    const float* W    = (const float*)d_in[1];
    const float* bias = (const float*)d_in[2];
    float* out = (float*)d_out;

    const int F = 800;
    const int B = in_sizes[0] / F;      // 32
    const int N = out_size / 3;         // 6,144,000
    const int S = N / B;                // 192,000
    const int upp = S / F;              // 240

    frame_prefix_kernel<<<B, 32>>>(f0, F, upp);

    dim3 gridB(F, B);
    har_uv_kernel<<<gridB, upp>>>(f0, W, bias, out, F, upp, N);

    const int nThreads = N / 4;         // 4 elements per thread
    noise_kernel<<<(nThreads + 255) / 256, 256>>>(out, N);
}

// round 4
// speedup vs baseline: 1.8982x; 1.8982x over previous
#include <cuda_runtime.h>
#include <stdint.h>

// Problem: NSF sine-source generator.
// Inputs: f0 [32,800] f32, W [9,1] f32, b [1] f32, upp=240 (int)
// Output: concat( har [32*192000], noise [32*192000], uv [32*192000] ) f32

#define SR_F 24000.0f
#define TWO_PI_F 6.2831853071795864769f

__device__ double g_prefix[32 * 800]; // exclusive frame prefix * upp (double)

// ---------------------------------------------------------------------------
// Kernel A: one WARP per batch row. 800 frames = 25 chunks of 32.
// All 25 loads issued up-front (MLP=25), then shuffle-based double scan.
// Same per-row left-to-right summation order as before -> identical numerics.
// ---------------------------------------------------------------------------
__global__ void frame_prefix_kernel(const float* __restrict__ f0, int F, int upp) {
    const int b = blockIdx.x;
    const int lane = threadIdx.x;          // 0..31
    const float* row = f0 + b * F;

    // Prefetch all chunks (coalesced, independent loads)
    float cf[25];
    #pragma unroll
    for (int k = 0; k < 25; k++)
        cf[k] = row[k * 32 + lane] / SR_F;  // f32 division rounding

    double carry = 0.0;
    const double uppd = (double)upp;
    #pragma unroll
    for (int k = 0; k < 25; k++) {
        double c = (double)cf[k];
        // inclusive warp scan (double shuffles)
        #pragma unroll
        for (int off = 1; off < 32; off <<= 1) {
            double v = __shfl_up_sync(0xffffffffu, c, off);
            if (lane >= off) c += v;
        }
        double excl = __shfl_up_sync(0xffffffffu, c, 1);
        if (lane == 0) excl = 0.0;
        g_prefix[b * F + k * 32 + lane] = (carry + excl) * uppd;
        carry += __shfl_sync(0xffffffffu, c, 31);   // chunk total
    }
}

// ---------------------------------------------------------------------------
// Kernel B: harmonic source + uv. Grid (F, B), blockDim = upp (=240).
// out index = (b*F + f)*upp + i -> fully coalesced, no integer divides.
// sin(h*theta) h=1..9 via Chebyshev recurrence from one sincosf.
// (Validated: rel_err 5.3e-6.)
// ---------------------------------------------------------------------------
__global__ void har_uv_kernel(const float* __restrict__ f0,
                              const float* __restrict__ W,
                              const float* __restrict__ bias,
                              float* __restrict__ out,
                              int F, int upp, int N) {
    const int f = blockIdx.x;
    const int b = blockIdx.y;
    const int i = threadIdx.x;           // 0..upp-1
    const int fr = b * F + f;

    const float f0v = __ldg(&f0[fr]);
    const float uv = (f0v > 0.0f) ? 1.0f : 0.0f;
    const float c  = f0v / SR_F;

    const double base = g_prefix[fr] + (double)c * (double)(i + 1);
    const float basef = (float)base;                 // reference holds f32 base_phase
    const float theta = basef * TWO_PI_F;

    float s1, c1;
    sincosf(theta, &s1, &c1);
    const float c2 = 2.0f * c1;

    float sprev = 0.0f, scur = s1;
    float acc = 0.0f;
    #pragma unroll
    for (int h = 0; h < 9; h++) {
        acc = fmaf(0.1f * scur, __ldg(&W[h]), acc);  // SINE_AMP*sin(h*th)*W_h
        float snext = fmaf(c2, scur, -sprev);        // sin((h+1)*th)
        sprev = scur; scur = snext;
    }

    const float har = tanhf(fmaf(uv, acc, __ldg(bias)));  // uv in {0,1}
    const int idx = fr * upp + i;
    out[idx]         = har;   // har_source
    out[2 * N + idx] = uv;    // uv
}

// ---------------------------------------------------------------------------
// Kernel C: noise = jax.random.normal(key(1234)) * (0.1/3)
// PARTITIONABLE threefry (modern jax default): element i uses counter
// (hi,lo) = (0, i); 32-bit output = out_lane0 ^ out_lane1. (Validated.)
// ---------------------------------------------------------------------------
__device__ __forceinline__ uint32_t threefry_xor(uint32_t p0, uint32_t p1) {
    const uint32_t k0 = 0u, k1 = 1234u;
    const uint32_t k2 = k0 ^ k1 ^ 0x1BD11BDAu;
    uint32_t x0 = p0 + k0, x1 = p1 + k1;
#define TF_MIX(r) { x0 += x1; x1 = (x1 << (r)) | (x1 >> (32 - (r))); x1 ^= x0; }
    TF_MIX(13) TF_MIX(15) TF_MIX(26) TF_MIX(6)   x0 += k1; x1 += k2 + 1u;
    TF_MIX(17) TF_MIX(29) TF_MIX(16) TF_MIX(24)  x0 += k2; x1 += k0 + 2u;
    TF_MIX(13) TF_MIX(15) TF_MIX(26) TF_MIX(6)   x0 += k0; x1 += k1 + 3u;
    TF_MIX(17) TF_MIX(29) TF_MIX(16) TF_MIX(24)  x0 += k1; x1 += k2 + 4u;
    TF_MIX(13) TF_MIX(15) TF_MIX(26) TF_MIX(6)   x0 += k2; x1 += k0 + 5u;
#undef TF_MIX
    return x0 ^ x1;
}

__device__ __forceinline__ float bits_to_noise(uint32_t bits) {
    float u01 = __uint_as_float((bits >> 9) | 0x3f800000u) - 1.0f; // [0,1)
    const float lo = -0.99999994f;             // nextafterf(-1,0)
    float u = u01 * 2.0f + lo;                 // (hi-lo) rounds to 2.0f
    u = fmaxf(lo, u);
    float n = 1.4142135623730951f * erfinvf(u);
    return n * (float)(0.1 / 3.0);
}

__global__ void noise_kernel(float* __restrict__ out, int N) {
    const int i = (blockIdx.x * blockDim.x + threadIdx.x) * 4;
    if (i >= N) return;
    float4 v;
    v.x = bits_to_noise(threefry_xor(0u, (uint32_t)(i + 0)));
    v.y = bits_to_noise(threefry_xor(0u, (uint32_t)(i + 1)));
    v.z = bits_to_noise(threefry_xor(0u, (uint32_t)(i + 2)));
    v.w = bits_to_noise(threefry_xor(0u, (uint32_t)(i + 3)));
    *(float4*)(out + N + i) = v;
}

// ---------------------------------------------------------------------------
extern "C" void kernel_launch(void* const* d_in, const int* in_sizes, int n_in,
                              void* d_out, int out_size) {
    const float* f0   = (const float*)d_in[0];
    const float* W    = (const float*)d_in[1];
    const float* bias = (const float*)d_in[2];
    float* out = (float*)d_out;

    const int F = 800;
    const int B = in_sizes[0] / F;      // 32
    const int N = out_size / 3;         // 6,144,000
    const int S = N / B;                // 192,000
    const int upp = S / F;              // 240

    frame_prefix_kernel<<<B, 32>>>(f0, F, upp);

    dim3 gridB(F, B);
    har_uv_kernel<<<gridB, upp>>>(f0, W, bias, out, F, upp, N);

    const int nThreads = N / 4;         // 4 elements per thread
    noise_kernel<<<(nThreads + 255) / 256, 256>>>(out, N);
}

// round 5
// speedup vs baseline: 3.3196x; 1.7488x over previous
#include <cuda_runtime.h>
#include <stdint.h>
#include <math.h>

// NSF sine-source generator.
// Inputs: f0 [32,800] f32, W [9,1] f32, b [1] f32, upp=240
// Output: concat( har [N], noise [N], uv [N] ) f32, N = 32*192000

#define SR_F 24000.0f

// frac(prefix * upp) per frame, split hi/lo so the hot kernel is FP64-free.
__device__ float2 g_prefix2[32 * 800];

// ---------------------------------------------------------------------------
// Kernel A: one warp per row. Lane l sums frames [25l, 25l+25) serially in
// double, warp-scan of lane totals, second pass writes frac(prefix*240) hi/lo.
// ---------------------------------------------------------------------------
__global__ void frame_prefix_kernel(const float* __restrict__ f0, int F, int upp) {
    const int b = blockIdx.x;
    const int lane = threadIdx.x;              // 0..31
    const float* row = f0 + b * F;

    float cf[25];
    #pragma unroll
    for (int j = 0; j < 25; j++)
        cf[j] = row[lane * 25 + j] / SR_F;     // f32 division rounding

    double s = 0.0;
    #pragma unroll
    for (int j = 0; j < 25; j++) s += (double)cf[j];

    // inclusive scan of lane totals -> exclusive
    double inc = s;
    #pragma unroll
    for (int off = 1; off < 32; off <<= 1) {
        double v = __shfl_up_sync(0xffffffffu, inc, off);
        if (lane >= off) inc += v;
    }
    double acc = inc - s;                       // prefix before this lane's segment

    const double uppd = (double)upp;
    const int base = b * F + lane * 25;
    #pragma unroll
    for (int j = 0; j < 25; j++) {
        double p  = acc * uppd;                 // prefix*upp for this frame
        double fd = p - floor(p);               // frac, exact in double
        float  hi = (float)fd;
        float  lo = (float)(fd - (double)hi);
        g_prefix2[base + j] = make_float2(hi, lo);
        acc += (double)cf[j];
    }
}

// ---------------------------------------------------------------------------
// threefry2x32 partitionable: element i -> counter (0, i), out = lane0 ^ lane1
// ---------------------------------------------------------------------------
__device__ __forceinline__ uint32_t threefry_xor(uint32_t p1) {
    const uint32_t k0 = 0u, k1 = 1234u;
    const uint32_t k2 = k0 ^ k1 ^ 0x1BD11BDAu;
    uint32_t x0 = 0u + k0, x1 = p1 + k1;
#define TF_MIX(r) { x0 += x1; x1 = (x1 << (r)) | (x1 >> (32 - (r))); x1 ^= x0; }
    TF_MIX(13) TF_MIX(15) TF_MIX(26) TF_MIX(6)   x0 += k1; x1 += k2 + 1u;
    TF_MIX(17) TF_MIX(29) TF_MIX(16) TF_MIX(24)  x0 += k2; x1 += k0 + 2u;
    TF_MIX(13) TF_MIX(15) TF_MIX(26) TF_MIX(6)   x0 += k0; x1 += k1 + 3u;
    TF_MIX(17) TF_MIX(29) TF_MIX(16) TF_MIX(24)  x0 += k1; x1 += k2 + 4u;
    TF_MIX(13) TF_MIX(15) TF_MIX(26) TF_MIX(6)   x0 += k2; x1 += k0 + 5u;
#undef TF_MIX
    return x0 ^ x1;
}

__device__ __forceinline__ float bits_to_noise(uint32_t bits) {
    float u01 = __uint_as_float((bits >> 9) | 0x3f800000u) - 1.0f;
    const float lo = -0.99999994f;               // nextafterf(-1,0)
    float u = u01 * 2.0f + lo;
    u = fmaxf(lo, u);
    float n = 1.4142135623730951f * erfinvf(u);
    return n * (float)(0.1 / 3.0);
}

// ---------------------------------------------------------------------------
// Fused kernel: har + uv + noise. Grid (F, B), 120 threads, 2 samples/thread.
// Phase: m = frac(prefix*upp) + c*(i+1), reduced to [-0.5,0.5) -> MUFU sincos.
// sin(h*theta) h=1..9 via Chebyshev recurrence. FP64-free.
// ---------------------------------------------------------------------------
__device__ __forceinline__ float har_sample(float hi, float lo, float c, int ip1,
                                            const float* w, float bb, float uvv) {
    float m = hi + (lo + c * (float)ip1);
    m -= floorf(m);                              // [0,1): sin is periodic, any wrap ok
    if (m >= 0.5f) m -= 1.0f;                    // [-0.5, 0.5)
    const float th = m * 6.2831853071795864769f; // theta in [-pi, pi)

    float s1 = __sinf(th);
    float c1 = __cosf(th);
    const float c2 = 2.0f * c1;

    float sprev = 0.0f, scur = s1, acc = 0.0f;
    #pragma unroll
    for (int h = 0; h < 9; h++) {
        acc = fmaf(scur, w[h], acc);             // w already holds 0.1*W_h
        float snext = fmaf(c2, scur, -sprev);
        sprev = scur; scur = snext;
    }
    return tanhf(fmaf(uvv, acc, bb));
}

__global__ void fused_kernel(const float* __restrict__ f0,
                             const float* __restrict__ W,
                             const float* __restrict__ bias,
                             float* __restrict__ out,
                             int F, int N) {
    const int f = blockIdx.x;
    const int b = blockIdx.y;
    const int t = threadIdx.x;                   // 0..119
    const int fr = b * F + f;

    const float f0v = __ldg(&f0[fr]);
    const float uvv = (f0v > 0.0f) ? 1.0f : 0.0f;
    const float c   = __fdividef(f0v, SR_F);
    const float2 pf = g_prefix2[fr];

    float w[9];
    #pragma unroll
    for (int h = 0; h < 9; h++) w[h] = 0.1f * __ldg(&W[h]);
    const float bb = __ldg(bias);

    const int i0  = 2 * t;                       // sample within frame
    const int idx = fr * 240 + i0;               // linear sample index

    const float h0 = har_sample(pf.x, pf.y, c, i0 + 1, w, bb, uvv);
    const float h1 = har_sample(pf.x, pf.y, c, i0 + 2, w, bb, uvv);

    const float n0 = bits_to_noise(threefry_xor((uint32_t)idx));
    const float n1 = bits_to_noise(threefry_xor((uint32_t)(idx + 1)));

    *(float2*)(out + idx)         = make_float2(h0, h1);   // har
    *(float2*)(out + N + idx)     = make_float2(n0, n1);   // noise
    *(float2*)(out + 2 * N + idx) = make_float2(uvv, uvv); // uv
}

// ---------------------------------------------------------------------------
extern "C" void kernel_launch(void* const* d_in, const int* in_sizes, int n_in,
                              void* d_out, int out_size) {
    const float* f0   = (const float*)d_in[0];
    const float* W    = (const float*)d_in[1];
    const float* bias = (const float*)d_in[2];
    float* out = (float*)d_out;

    const int F = 800;
    const int B = in_sizes[0] / F;      // 32
    const int N = out_size / 3;         // 6,144,000
    const int upp = (N / B) / F;        // 240

    frame_prefix_kernel<<<B, 32>>>(f0, F, upp);

    dim3 grid(F, B);
    fused_kernel<<<grid, 120>>>(f0, W, bias, out, F, N);
}

// round 7
// speedup vs baseline: 3.7699x; 1.1357x over previous
#include <cuda_runtime.h>
#include <stdint.h>
#include <math.h>

// NSF sine-source generator.
// Inputs: f0 [32,800] f32, W [9,1] f32, b [1] f32, upp=240
// Output: concat( har [N], noise [N], uv [N] ) f32, N = 32*192000

#define SR_F 24000.0f
#define TWO_PI_F 6.2831853071795864769f

// frac(prefix * upp) per frame as float-float (hi, lo).
__device__ float2 g_prefix2[32 * 800];

// ---------------------------------------------------------------------------
// Kernel A: one warp per row, pure FP32 compensated (2sum) arithmetic.
// Lane l owns frames [25l, 25l+25). Serial chain is FADD lat-4, not DADD.
// ---------------------------------------------------------------------------
__global__ void frame_prefix_kernel(const float* __restrict__ f0, int F) {
    const int b = blockIdx.x;
    const int lane = threadIdx.x;              // 0..31
    const float* row = f0 + b * F;

    float cf[25];
    #pragma unroll
    for (int j = 0; j < 25; j++)
        cf[j] = row[lane * 25 + j] / SR_F;     // f32 division rounding

    // per-lane compensated total (s, e)
    float s = 0.0f, e = 0.0f;
    #pragma unroll
    for (int j = 0; j < 25; j++) {
        float c = cf[j];
        float t = s + c;
        float z = t - s;
        e += (s - (t - z)) + (c - z);          // exact 2sum residual
        s = t;
    }

    // inclusive warp scan on (s, e)
    #pragma unroll
    for (int off = 1; off < 32; off <<= 1) {
        float so = __shfl_up_sync(0xffffffffu, s, off);
        float eo = __shfl_up_sync(0xffffffffu, e, off);
        if (lane >= off) {
            float t = s + so;
            float z = t - s;
            e += eo + (s - (t - z)) + (so - z);
            s = t;
        }
    }
    // exclusive
    float sx = __shfl_up_sync(0xffffffffu, s, 1);
    float ex = __shfl_up_sync(0xffffffffu, e, 1);
    if (lane == 0) { sx = 0.0f; ex = 0.0f; }

    const int base = b * F + lane * 25;
    #pragma unroll
    for (int j = 0; j < 25; j++) {
        // p = (sx, ex) * 240 via 2prod
        float ph = sx * 240.0f;
        float pl = fmaf(sx, 240.0f, -ph) + ex * 240.0f;
        float fl = floorf(ph + pl);
        g_prefix2[base + j] = make_float2(ph - fl, pl);  // frac, downstream re-wraps
        // running += cf[j] (2sum)
        float c = cf[j];
        float t = sx + c;
        float z = t - sx;
        ex += (sx - (t - z)) + (c - z);
        sx = t;
    }
}

// ---------------------------------------------------------------------------
// threefry2x32 partitionable: element i -> counter (0, i), out = lane0 ^ lane1
// ---------------------------------------------------------------------------
__device__ __forceinline__ uint32_t threefry_xor(uint32_t p1) {
    const uint32_t k0 = 0u, k1 = 1234u;
    const uint32_t k2 = k0 ^ k1 ^ 0x1BD11BDAu;
    uint32_t x0 = 0u + k0, x1 = p1 + k1;
#define TF_MIX(r) { x0 += x1; x1 = (x1 << (r)) | (x1 >> (32 - (r))); x1 ^= x0; }
    TF_MIX(13) TF_MIX(15) TF_MIX(26) TF_MIX(6)   x0 += k1; x1 += k2 + 1u;
    TF_MIX(17) TF_MIX(29) TF_MIX(16) TF_MIX(24)  x0 += k2; x1 += k0 + 2u;
    TF_MIX(13) TF_MIX(15) TF_MIX(26) TF_MIX(6)   x0 += k0; x1 += k1 + 3u;
    TF_MIX(17) TF_MIX(29) TF_MIX(16) TF_MIX(24)  x0 += k1; x1 += k2 + 4u;
    TF_MIX(13) TF_MIX(15) TF_MIX(26) TF_MIX(6)   x0 += k2; x1 += k0 + 5u;
#undef TF_MIX
    return x0 ^ x1;
}

// Giles (2010) single-precision erfinv with fast log; returns
// sqrt(2)*erfinv(x) * (0.1/3) folded into one scale.
__device__ __forceinline__ float erfinv_scaled(float x) {
    float w = -__logf(fmaf(-x, x, 1.0f));
    float p;
    if (w < 5.0f) {
        w -= 2.5f;
        p =            2.81022636e-08f;
        p = fmaf(p, w, 3.43273939e-07f);
        p = fmaf(p, w, -3.5233877e-06f);
        p = fmaf(p, w, -4.39150654e-06f);
        p = fmaf(p, w, 0.00021858087f);
        p = fmaf(p, w, -0.00125372503f);
        p = fmaf(p, w, -0.00417768164f);
        p = fmaf(p, w, 0.246640727f);
        p = fmaf(p, w, 1.50140941f);
    } else {
        w = sqrtf(w) - 3.0f;
        p =            -0.000200214257f;
        p = fmaf(p, w, 0.000100950558f);
        p = fmaf(p, w, 0.00134934322f);
        p = fmaf(p, w, -0.00367342844f);
        p = fmaf(p, w, 0.00573950773f);
        p = fmaf(p, w, -0.0076224613f);
        p = fmaf(p, w, 0.00943887047f);
        p = fmaf(p, w, 1.00167406f);
        p = fmaf(p, w, 2.83297682f);
    }
    return p * x * 0.047140452079103168f;   // sqrt(2)*0.1/3
}

__device__ __forceinline__ float bits_to_noise(uint32_t bits) {
    float u01 = __uint_as_float((bits >> 9) | 0x3f800000u) - 1.0f;
    const float lo = -0.99999994f;             // nextafterf(-1,0)
    float u = fmaxf(lo, u01 * 2.0f + lo);
    return erfinv_scaled(u);
}

// ---------------------------------------------------------------------------
// Fused kernel: har + uv + noise. Grid (F/4, B), 240 threads.
// Thread t -> frame f4*4 + t/60, samples i0..i0+3 with i0 = (t%60)*4.
// ---------------------------------------------------------------------------
__device__ __forceinline__ float har_sample(float hi, float lo, float c, int ip1,
                                            const float* w, float bb, float uvv) {
    float m = hi + (lo + c * (float)ip1);      // m in (-1e-7, 1.02)
    m -= (m >= 0.5f) ? 1.0f : 0.0f;            // -> [-0.5, 0.52); sin periodic
    const float th = m * TWO_PI_F;

    float s1 = __sinf(th);
    float c1 = __cosf(th);
    const float c2 = 2.0f * c1;

    float sprev = 0.0f, scur = s1, acc = 0.0f;
    #pragma unroll
    for (int h = 0; h < 9; h++) {
        acc = fmaf(scur, w[h], acc);           // w holds 0.1*W_h
        float snext = fmaf(c2, scur, -sprev);
        sprev = scur; scur = snext;
    }
    // tanh(x) = 1 - 2/(e^{2x}+1)
    const float x = fmaf(uvv, acc, bb);
    const float eg = __expf(2.0f * x);
    return 1.0f - __fdividef(2.0f, eg + 1.0f);
}

__global__ void fused_kernel(const float* __restrict__ f0,
                             const float* __restrict__ W,
                             const float* __restrict__ bias,
                             float* __restrict__ out,
                             int F, int N) {
    const int f4 = blockIdx.x;                 // 0..F/4-1
    const int b  = blockIdx.y;
    const int t  = threadIdx.x;                // 0..239
    const int fi = t / 60;                     // frame within quad
    const int i0 = (t - fi * 60) * 4;          // sample within frame
    const int fr = b * F + f4 * 4 + fi;

    const float f0v = __ldg(&f0[fr]);
    const float uvv = (f0v > 0.0f) ? 1.0f : 0.0f;
    const float c   = __fdividef(f0v, SR_F);
    const float2 pf = g_prefix2[fr];

    float w[9];
    #pragma unroll
    for (int h = 0; h < 9; h++) w[h] = 0.1f * __ldg(&W[h]);
    const float bb = __ldg(bias);

    const int idx = fr * 240 + i0;

    float4 noi;
    noi.x = bits_to_noise(threefry_xor((uint32_t)(idx + 0)));
    noi.y = bits_to_noise(threefry_xor((uint32_t)(idx + 1)));
    noi.z = bits_to_noise(threefry_xor((uint32_t)(idx + 2)));
    noi.w = bits_to_noise(threefry_xor((uint32_t)(idx + 3)));

    float4 har;
    har.x = har_sample(pf.x, pf.y, c, i0 + 1, w, bb, uvv);
    har.y = har_sample(pf.x, pf.y, c, i0 + 2, w, bb, uvv);
    har.z = har_sample(pf.x, pf.y, c, i0 + 3, w, bb, uvv);
    har.w = har_sample(pf.x, pf.y, c, i0 + 4, w, bb, uvv);

    *(float4*)(out + idx)         = har;
    *(float4*)(out + N + idx)     = noi;
    *(float4*)(out + 2 * N + idx) = make_float4(uvv, uvv, uvv, uvv);
}

// ---------------------------------------------------------------------------
extern "C" void kernel_launch(void* const* d_in, const int* in_sizes, int n_in,
                              void* d_out, int out_size) {
    const float* f0   = (const float*)d_in[0];
    const float* W    = (const float*)d_in[1];
    const float* bias = (const float*)d_in[2];
    float* out = (float*)d_out;

    const int F = 800;
    const int B = in_sizes[0] / F;      // 32
    const int N = out_size / 3;         // 6,144,000

    frame_prefix_kernel<<<B, 32>>>(f0, F);

    dim3 grid(F / 4, B);
    fused_kernel<<<grid, 240>>>(f0, W, bias, out, F, N);
}

// round 8
// speedup vs baseline: 3.9495x; 1.0476x over previous
#include <cuda_runtime.h>
#include <stdint.h>
#include <math.h>

// NSF sine-source generator.
// Inputs: f0 [32,800] f32, W [9,1] f32, b [1] f32, upp=240
// Output: concat( har [N], noise [N], uv [N] ) f32, N = 32*192000

#define SR_F 24000.0f
#define TWO_PI_F 6.2831853071795864769f

// frac(prefix * upp) per frame as float-float (hi, lo).
__device__ float2 g_prefix2[32 * 800];

// ---------------------------------------------------------------------------
// Kernel A: one warp per row, FP32 compensated (2sum) arithmetic. (validated)
// ---------------------------------------------------------------------------
__global__ void frame_prefix_kernel(const float* __restrict__ f0, int F) {
    const int b = blockIdx.x;
    const int lane = threadIdx.x;
    const float* row = f0 + b * F;

    float cf[25];
    #pragma unroll
    for (int j = 0; j < 25; j++)
        cf[j] = row[lane * 25 + j] / SR_F;

    float s = 0.0f, e = 0.0f;
    #pragma unroll
    for (int j = 0; j < 25; j++) {
        float c = cf[j];
        float t = s + c;
        float z = t - s;
        e += (s - (t - z)) + (c - z);
        s = t;
    }
    #pragma unroll
    for (int off = 1; off < 32; off <<= 1) {
        float so = __shfl_up_sync(0xffffffffu, s, off);
        float eo = __shfl_up_sync(0xffffffffu, e, off);
        if (lane >= off) {
            float t = s + so;
            float z = t - s;
            e += eo + (s - (t - z)) + (so - z);
            s = t;
        }
    }
    float sx = __shfl_up_sync(0xffffffffu, s, 1);
    float ex = __shfl_up_sync(0xffffffffu, e, 1);
    if (lane == 0) { sx = 0.0f; ex = 0.0f; }

    const int base = b * F + lane * 25;
    #pragma unroll
    for (int j = 0; j < 25; j++) {
        float ph = sx * 240.0f;
        float pl = fmaf(sx, 240.0f, -ph) + ex * 240.0f;
        float fl = floorf(ph + pl);
        g_prefix2[base + j] = make_float2(ph - fl, pl);
        float c = cf[j];
        float t = sx + c;
        float z = t - sx;
        ex += (sx - (t - z)) + (c - z);
        sx = t;
    }
}

// ---------------------------------------------------------------------------
// threefry2x32 partitionable: element i -> counter (0,i), out = x0 ^ x1.
// ---------------------------------------------------------------------------
__device__ __forceinline__ uint32_t threefry_xor(uint32_t p1) {
    const uint32_t k0 = 0u, k1 = 1234u;
    const uint32_t k2 = k0 ^ k1 ^ 0x1BD11BDAu;
    uint32_t x0 = 0u + k0, x1 = p1 + k1;
#define TF_MIX(r) { x0 += x1; x1 = (x1 << (r)) | (x1 >> (32 - (r))); x1 ^= x0; }
    TF_MIX(13) TF_MIX(15) TF_MIX(26) TF_MIX(6)   x0 += k1; x1 += k2 + 1u;
    TF_MIX(17) TF_MIX(29) TF_MIX(16) TF_MIX(24)  x0 += k2; x1 += k0 + 2u;
    TF_MIX(13) TF_MIX(15) TF_MIX(26) TF_MIX(6)   x0 += k0; x1 += k1 + 3u;
    TF_MIX(17) TF_MIX(29) TF_MIX(16) TF_MIX(24)  x0 += k1; x1 += k2 + 4u;
    TF_MIX(13) TF_MIX(15) TF_MIX(26) TF_MIX(6)   x0 += k2; x1 += k0 + 5u;
#undef TF_MIX
    return x0 ^ x1;
}

// Giles erfinv, sqrt(2)*0.1/3 folded.
__device__ __forceinline__ float erfinv_scaled(float x) {
    float w = -__logf(fmaf(-x, x, 1.0f));
    float p;
    if (w < 5.0f) {
        w -= 2.5f;
        p =            2.81022636e-08f;
        p = fmaf(p, w, 3.43273939e-07f);
        p = fmaf(p, w, -3.5233877e-06f);
        p = fmaf(p, w, -4.39150654e-06f);
        p = fmaf(p, w, 0.00021858087f);
        p = fmaf(p, w, -0.00125372503f);
        p = fmaf(p, w, -0.00417768164f);
        p = fmaf(p, w, 0.246640727f);
        p = fmaf(p, w, 1.50140941f);
    } else {
        w = sqrtf(w) - 3.0f;
        p =            -0.000200214257f;
        p = fmaf(p, w, 0.000100950558f);
        p = fmaf(p, w, 0.00134934322f);
        p = fmaf(p, w, -0.00367342844f);
        p = fmaf(p, w, 0.00573950773f);
        p = fmaf(p, w, -0.0076224613f);
        p = fmaf(p, w, 0.00943887047f);
        p = fmaf(p, w, 1.00167406f);
        p = fmaf(p, w, 2.83297682f);
    }
    return p * x * 0.047140452079103168f;
}

__device__ __forceinline__ float bits_to_noise(uint32_t bits) {
    float v = __uint_as_float((bits >> 9) | 0x3f800000u);   // [1,2)
    const float lo = -0.99999994f;                           // nextafterf(-1,0)
    float u = fmaxf(lo, fmaf(v, 2.0f, -3.0f));               // == (v-1)*2 + lo (±1ulp)
    return erfinv_scaled(u);
}

// Chebyshev harmonic sum + tanh from (sin, cos) of theta.
__device__ __forceinline__ float cheby_tanh(float s1, float c1,
                                            const float* w, float bb, float uvv) {
    const float c2 = 2.0f * c1;
    float sprev = 0.0f, scur = s1, acc = 0.0f;
    #pragma unroll
    for (int h = 0; h < 9; h++) {
        acc = fmaf(scur, w[h], acc);
        float snext = fmaf(c2, scur, -sprev);
        sprev = scur; scur = snext;
    }
    const float x = fmaf(uvv, acc, bb);
    const float eg = __expf(x + x);
    return 1.0f - __fdividef(2.0f, eg + 1.0f);
}

// ---------------------------------------------------------------------------
// Fused kernel: har + uv + noise. Grid (F/8, B), 240 threads, 8 samples/thr.
// Thread t -> frame fi = t/30, samples i0 = (t%30)*8 .. +7.
// ---------------------------------------------------------------------------
__global__ void __launch_bounds__(240, 7)
fused_kernel(const float* __restrict__ f0,
             const float* __restrict__ W,
             const float* __restrict__ bias,
             float* __restrict__ out,
             int F, int N) {
    const int f8 = blockIdx.x;                 // 0..F/8-1
    const int b  = blockIdx.y;
    const int t  = threadIdx.x;                // 0..239
    const int fi = t / 30;
    const int i0 = (t - fi * 30) * 8;
    const int fr = b * F + f8 * 8 + fi;

    const float f0v = __ldg(&f0[fr]);
    const float uvv = (f0v > 0.0f) ? 1.0f : 0.0f;
    const float c   = __fdividef(f0v, SR_F);
    const float2 pf = g_prefix2[fr];
    const float bb  = __ldg(bias);

    float w[9];
    #pragma unroll
    for (int h = 0; h < 9; h++) w[h] = 0.1f * __ldg(&W[h]);

    const uint32_t idx = (uint32_t)fr * 240u + (uint32_t)i0;
    float* __restrict__ harp = out + idx;
    float* __restrict__ noip = out + N + idx;
    float* __restrict__ uvp  = out + 2 * N + idx;

    // ---- noise (8 independent hashes; store quads promptly) ----
    {
        float4 nq;
        nq.x = bits_to_noise(threefry_xor(idx + 0u));
        nq.y = bits_to_noise(threefry_xor(idx + 1u));
        nq.z = bits_to_noise(threefry_xor(idx + 2u));
        nq.w = bits_to_noise(threefry_xor(idx + 3u));
        *(float4*)noip = nq;
        nq.x = bits_to_noise(threefry_xor(idx + 4u));
        nq.y = bits_to_noise(threefry_xor(idx + 5u));
        nq.z = bits_to_noise(threefry_xor(idx + 6u));
        nq.w = bits_to_noise(threefry_xor(idx + 7u));
        *(float4*)(noip + 4) = nq;
    }

    // ---- har via one sincos + rotation by delta = 2*pi*c per sample ----
    {
        float m = pf.x + (pf.y + c * (float)(i0 + 1));
        m -= (m >= 0.5f) ? 1.0f : 0.0f;        // one period wrap
        const float th = m * TWO_PI_F;
        float s  = __sinf(th);
        float co = __cosf(th);
        const float dm = c * TWO_PI_F;
        const float sc = __sinf(dm);
        const float cc = __cosf(dm);

        float4 hq;
        #pragma unroll
        for (int q = 0; q < 2; q++) {
            #pragma unroll
            for (int k = 0; k < 4; k++) {
                (&hq.x)[k] = cheby_tanh(s, co, w, bb, uvv);
                float sn = fmaf(s, cc, co * sc);
                float cn = fmaf(co, cc, -(s * sc));
                s = sn; co = cn;
            }
            *(float4*)(harp + 4 * q) = hq;
        }
    }

    const float4 uq = make_float4(uvv, uvv, uvv, uvv);
    *(float4*)uvp       = uq;
    *(float4*)(uvp + 4) = uq;
}

// ---------------------------------------------------------------------------
extern "C" void kernel_launch(void* const* d_in, const int* in_sizes, int n_in,
                              void* d_out, int out_size) {
    const float* f0   = (const float*)d_in[0];
    const float* W    = (const float*)d_in[1];
    const float* bias = (const float*)d_in[2];
    float* out = (float*)d_out;

    const int F = 800;
    const int B = in_sizes[0] / F;      // 32
    const int N = out_size / 3;         // 6,144,000

    frame_prefix_kernel<<<B, 32>>>(f0, F);

    dim3 grid(F / 8, B);
    fused_kernel<<<grid, 240>>>(f0, W, bias, out, F, N);
}